// round 1
// baseline (speedup 1.0000x reference)
#include <cuda_runtime.h>
#include <cstring>

// Closed-form solution: dynamics are affine (X' = A X + b per component),
// so 8 RK4 substeps collapse to X_final = R8 * X0 + T * b with
//   R  = I + hA + (hA)^2/2 + (hA)^3/6 + (hA)^4/24   (exact RK4 one-step map)
//   S  = h (I + hA/2 + (hA)^2/6 + (hA)^3/24)
//   R8 = R^8,  T = (sum_{k=0}^{7} R^k) * S,  b = (0, g, c*u)
// Constants computed on host in double, applied in fp32 on device.

struct Coef {
    float a01, a02, a12, a22;   // R8 entries (upper-triangular, unit diag on rows 0,1)
    float u0, u1, u2;           // c * T[:,2]  (coefficient of U)
    float d0, d1, d2;           // 9.81 * T[:,1] (gravity, z-component only)
};

#define ENVS_PER_BLOCK 256
#define X_FLOATS (ENVS_PER_BLOCK * 9)   // 2304
#define U_FLOATS (ENVS_PER_BLOCK * 3)   // 768
#define X_VEC4   (X_FLOATS / 4)         // 576
#define U_VEC4   (U_FLOATS / 4)         // 192

__global__ void __launch_bounds__(ENVS_PER_BLOCK)
pointmass_kernel(const float4* __restrict__ x0v,
                 const float4* __restrict__ uv,
                 float4* __restrict__ outv,
                 Coef C,
                 int n_x_vec4, int n_u_vec4)
{
    __shared__ float4 sx4[X_VEC4];
    __shared__ float4 su4[U_VEC4];
    float* sx = reinterpret_cast<float*>(sx4);
    float* su = reinterpret_cast<float*>(su4);

    const int tid = threadIdx.x;
    const size_t xbase = (size_t)blockIdx.x * X_VEC4;
    const size_t ubase = (size_t)blockIdx.x * U_VEC4;

    // Coalesced vector loads into shared memory.
    #pragma unroll
    for (int i = tid; i < X_VEC4; i += ENVS_PER_BLOCK) {
        size_t g = xbase + i;
        if (g < (size_t)n_x_vec4) sx4[i] = x0v[g];
    }
    #pragma unroll
    for (int i = tid; i < U_VEC4; i += ENVS_PER_BLOCK) {
        size_t g = ubase + i;
        if (g < (size_t)n_u_vec4) su4[i] = uv[g];
    }
    __syncthreads();

    // One env per thread. smem read stride 9 / 3 -> gcd with 32 is 1 -> conflict-free.
    {
        float* xp = sx + tid * 9;
        const float* up = su + tid * 3;

        #pragma unroll
        for (int f = 0; f < 3; f++) {
            float p = xp[f];
            float v = xp[f + 3];
            float a = xp[f + 6];
            float u = up[f];

            float np = fmaf(C.a01, v, fmaf(C.a02, a, fmaf(C.u0, u, p)));
            float nv = fmaf(C.a12, a, fmaf(C.u1, u, v));
            float na = fmaf(C.a22, a, C.u2 * u);
            if (f == 2) { np += C.d0; nv += C.d1; na += C.d2; }

            xp[f]     = np;
            xp[f + 3] = nv;
            xp[f + 6] = na;
        }
    }
    __syncthreads();

    // Coalesced vector stores.
    #pragma unroll
    for (int i = tid; i < X_VEC4; i += ENVS_PER_BLOCK) {
        size_t g = xbase + i;
        if (g < (size_t)n_x_vec4) outv[g] = sx4[i];
    }
}

// ---------------- host-side 3x3 double matrix helpers ----------------

static void m_mul(const double A[3][3], const double B[3][3], double C[3][3]) {
    double T[3][3];
    for (int i = 0; i < 3; i++)
        for (int j = 0; j < 3; j++) {
            double s = 0.0;
            for (int k = 0; k < 3; k++) s += A[i][k] * B[k][j];
            T[i][j] = s;
        }
    std::memcpy(C, T, sizeof(T));
}

static void m_addscaled(double A[3][3], const double B[3][3], double s) {
    for (int i = 0; i < 3; i++)
        for (int j = 0; j < 3; j++) A[i][j] += s * B[i][j];
}

extern "C" void kernel_launch(void* const* d_in, const int* in_sizes, int n_in,
                              void* d_out, int out_size)
{
    const float4* x0v = (const float4*)d_in[0];
    const float4* uv  = (const float4*)d_in[1];
    float4* outv      = (float4*)d_out;

    const int n_envs = in_sizes[0] / 9;

    // ---- build closed-form coefficients in double ----
    const double DT = 0.02;
    const double h  = DT / 8.0;
    const double c  = 0.5 / DT;     // LMBDA / DT = 25
    const double g  = 9.81;         // -G_VEC z component

    double I[3][3]  = {{1,0,0},{0,1,0},{0,0,1}};
    double hA[3][3] = {{0,h,0},{0,0,h},{0,0,-h*c}};

    double H2[3][3], H3[3][3], H4[3][3];
    m_mul(hA, hA, H2);
    m_mul(H2, hA, H3);
    m_mul(H3, hA, H4);

    // R = I + hA + H2/2 + H3/6 + H4/24
    double R[3][3];
    std::memcpy(R, I, sizeof(R));
    m_addscaled(R, hA, 1.0);
    m_addscaled(R, H2, 1.0/2.0);
    m_addscaled(R, H3, 1.0/6.0);
    m_addscaled(R, H4, 1.0/24.0);

    // S = h*(I + hA/2 + H2/6 + H3/24)
    double S[3][3];
    std::memcpy(S, I, sizeof(S));
    m_addscaled(S, hA, 1.0/2.0);
    m_addscaled(S, H2, 1.0/6.0);
    m_addscaled(S, H3, 1.0/24.0);
    for (int i = 0; i < 3; i++)
        for (int j = 0; j < 3; j++) S[i][j] *= h;

    // R8 = R^8 ; P = sum_{k=0}^{7} R^k
    double P[3][3], Rk[3][3];
    std::memcpy(P, I, sizeof(P));
    std::memcpy(Rk, I, sizeof(Rk));
    for (int k = 1; k < 8; k++) {
        m_mul(Rk, R, Rk);
        m_addscaled(P, Rk, 1.0);
    }
    double R8[3][3];
    m_mul(Rk, R, R8);   // Rk currently holds R^7

    // T = P * S
    double T[3][3];
    m_mul(P, S, T);

    Coef C;
    C.a01 = (float)R8[0][1];
    C.a02 = (float)R8[0][2];
    C.a12 = (float)R8[1][2];
    C.a22 = (float)R8[2][2];
    C.u0  = (float)(c * T[0][2]);
    C.u1  = (float)(c * T[1][2]);
    C.u2  = (float)(c * T[2][2]);
    C.d0  = (float)(g * T[0][1]);
    C.d1  = (float)(g * T[1][1]);
    C.d2  = (float)(g * T[2][1]);

    const int n_x_vec4 = (n_envs * 9) / 4;
    const int n_u_vec4 = (n_envs * 3) / 4;
    const int blocks   = (n_envs + ENVS_PER_BLOCK - 1) / ENVS_PER_BLOCK;

    pointmass_kernel<<<blocks, ENVS_PER_BLOCK>>>(x0v, uv, outv, C, n_x_vec4, n_u_vec4);
}